// round 13
// baseline (speedup 1.0000x reference)
#include <cuda_runtime.h>

#define Hh 32
#define Bb 64
#define Tt 16384
#define CHUNK 32
#define NCHUNK (Tt / CHUNK)

__device__ __forceinline__ unsigned long long pk2(float lo, float hi) {
    unsigned long long d; asm("mov.b64 %0,{%1,%2};" : "=l"(d) : "f"(lo), "f"(hi)); return d;
}
__device__ __forceinline__ void upk2(unsigned long long v, float& lo, float& hi) {
    asm("mov.b64 {%0,%1},%2;" : "=f"(lo), "=f"(hi) : "l"(v));
}
__device__ __forceinline__ unsigned long long ffma2(unsigned long long a, unsigned long long b, unsigned long long c) {
    unsigned long long d; asm("fma.rn.f32x2 %0,%1,%2,%3;" : "=l"(d) : "l"(a), "l"(b), "l"(c)); return d;
}
__device__ __forceinline__ unsigned long long fadd2(unsigned long long a, unsigned long long b) {
    unsigned long long d; asm("add.rn.f32x2 %0,%1,%2;" : "=l"(d) : "l"(a), "l"(b)); return d;
}
__device__ __forceinline__ float red2(unsigned long long a0, unsigned long long a1,
                                      unsigned long long a2, unsigned long long a3) {
    unsigned long long s = fadd2(fadd2(a0, a1), fadd2(a2, a3));
    float lo, hi; upk2(s, lo, hi);
    return lo + hi;
}

// hardware tanh (MUFU.TANH, lat ~16)
__device__ __forceinline__ float htanh(float z) {
    float t; asm("tanh.approx.f32 %0,%1;" : "=f"(t) : "f"(z));
    return t;
}

#define LOADPN(sa_, P) \
    unsigned long long P##0,P##1,P##2,P##3,P##4,P##5,P##6,P##7,P##8,P##9,P##a,P##b,P##c,P##d,P##e,P##f; \
    asm volatile("ld.shared.v2.u64 {%0,%1},[%2];"    : "=l"(P##0), "=l"(P##1) : "r"(sa_)); \
    asm volatile("ld.shared.v2.u64 {%0,%1},[%2+16];" : "=l"(P##2), "=l"(P##3) : "r"(sa_)); \
    asm volatile("ld.shared.v2.u64 {%0,%1},[%2+32];" : "=l"(P##4), "=l"(P##5) : "r"(sa_)); \
    asm volatile("ld.shared.v2.u64 {%0,%1},[%2+48];" : "=l"(P##6), "=l"(P##7) : "r"(sa_)); \
    asm volatile("ld.shared.v2.u64 {%0,%1},[%2+64];" : "=l"(P##8), "=l"(P##9) : "r"(sa_)); \
    asm volatile("ld.shared.v2.u64 {%0,%1},[%2+80];" : "=l"(P##a), "=l"(P##b) : "r"(sa_)); \
    asm volatile("ld.shared.v2.u64 {%0,%1},[%2+96];" : "=l"(P##c), "=l"(P##d) : "r"(sa_)); \
    asm volatile("ld.shared.v2.u64 {%0,%1},[%2+112];": "=l"(P##e), "=l"(P##f) : "r"(sa_));

#define DOT16N(w2, seed, res, P) { \
    unsigned long long a0 = pk2(seed, 0.f), a1 = 0ull, a2 = 0ull, a3 = 0ull; \
    a0 = ffma2(w2[0],  P##0, a0); a1 = ffma2(w2[1],  P##1, a1); \
    a2 = ffma2(w2[2],  P##2, a2); a3 = ffma2(w2[3],  P##3, a3); \
    a0 = ffma2(w2[4],  P##4, a0); a1 = ffma2(w2[5],  P##5, a1); \
    a2 = ffma2(w2[6],  P##6, a2); a3 = ffma2(w2[7],  P##7, a3); \
    a0 = ffma2(w2[8],  P##8, a0); a1 = ffma2(w2[9],  P##9, a1); \
    a2 = ffma2(w2[10], P##a, a2); a3 = ffma2(w2[11], P##b, a3); \
    a0 = ffma2(w2[12], P##c, a0); a1 = ffma2(w2[13], P##d, a1); \
    a2 = ffma2(w2[14], P##e, a2); a3 = ffma2(w2[15], P##f, a3); \
    res = red2(a0, a1, a2, a3); }

#define STSF(addr, val) asm volatile("st.shared.f32 [%0], %1;" :: "r"(addr), "f"(val))

// load packed weight rows (plain, unscaled)
__device__ __forceinline__ void load_w2(const float* __restrict__ W, int lane,
                                        unsigned long long* w2) {
    #pragma unroll
    for (int k = 0; k < 16; ++k)
        w2[k] = pk2(W[lane * Hh + 2 * k], W[lane * Hh + 2 * k + 1]);
}

__global__ __launch_bounds__(96, 1) void rnn_pipe_kernel(
    const float* __restrict__ x,        const float* __restrict__ h_state,
    const float* __restrict__ W_ih0,    const float* __restrict__ W_hh0,
    const float* __restrict__ b_ih0,    const float* __restrict__ b_hh0,
    const float* __restrict__ W_ih1,    const float* __restrict__ W_hh1,
    const float* __restrict__ b_ih1,    const float* __restrict__ b_hh1,
    const float* __restrict__ W_out,    const float* __restrict__ b_out,
    float* __restrict__ out)
{
    __shared__ __align__(16) float sh0[2][CHUNK][Hh];   // A -> B2 ring; ALSO A's step exchange
    __shared__ __align__(16) float su [2][CHUNK][Hh];   // B2 -> B1 (bias1 pre-folded)
    __shared__ float sh1[2][CHUNK][Hh + 1];             // B1 -> out stage (padded)
    __shared__ __align__(16) float hx1[Hh];             // warp B1 step exchange

    const int b    = blockIdx.x;
    const int lane = threadIdx.x & 31;
    const int wid  = threadIdx.x >> 5;

    if (wid == 0) {
        // ---- Warp A: layer-0 recurrence; exchange through the ring rows ----
        unsigned long long w2[16];
        load_w2(W_hh0, lane, w2);
        const float wi    = W_ih0[lane];
        const float bias0 = b_ih0[lane] + b_hh0[lane];
        float h = h_state[b * Hh + lane];
        unsigned int s0a = (unsigned int)__cvta_generic_to_shared(sh0);

        // Seed the exchange: pretend step -1 wrote buf1 row31 (overwritten in chunk 1
        // before B2 ever consumes chunk-1 data).
        unsigned int rd = s0a + (CHUNK * Hh * 4) + 31 * (Hh * 4);
        STSF(rd + lane * 4, h);

        const float* xb = x + (size_t)b * Tt;
        for (int g = 0; g < NCHUNK + 3; ++g) {
            if (g < NCHUNK) {
                const float* xg = xb + g * CHUNK;
                unsigned int wr = s0a + (g & 1) * (CHUNK * Hh * 4);
                #pragma unroll 16
                for (int s = 0; s < CHUNK; ++s) {
                    float xv = __ldg(xg + s);          // uniform addr: 1 sector, L1-hit
                    float xterm = fmaf(xv, wi, bias0); // off-chain
                    LOADPN(rd, U);                     // row written at step s-1
                    float z; DOT16N(w2, xterm, z, U);
                    h = htanh(z);
                    STSF(wr + lane * 4, h);            // chain STS doubles as ring write
                    rd = wr;
                    wr += Hh * 4;
                }
            }
            __syncthreads();
        }
        out[(size_t)Bb * Tt + b * Hh + lane] = h;                    // h_final L0

    } else if (wid == 1) {
        // ---- Warp B2: u-projection (bias1 folded) from h0 ring + output stage ----
        unsigned long long wu[16];
        load_w2(W_ih1, lane, wu);
        const float bias1 = b_ih1[lane] + b_hh1[lane];
        float wc[Hh];
        const float bo = b_out[0];
        #pragma unroll
        for (int k = 0; k < Hh; ++k) wc[k] = W_out[k];
        unsigned int s0a = (unsigned int)__cvta_generic_to_shared(sh0);
        float* ob = out + (size_t)b * Tt;

        for (int g = 0; g < NCHUNK + 3; ++g) {
            if (g >= 1 && g <= NCHUNK) {
                int buf = (g - 1) & 1;
                unsigned int base = s0a + buf * (CHUNK * Hh * 4);
                #pragma unroll 4
                for (int s = 0; s < CHUNK; ++s) {
                    LOADPN(base + s * (Hh * 4), U);
                    float uu; DOT16N(wu, bias1, uu, U);
                    su[buf][s][lane] = uu;
                }
            }
            if (g >= 3) {                               // output stage
                int gg  = g - 3;
                const float* hv = sh1[gg & 1][lane];    // lane = timestep in chunk
                float a0 = 0.f, a1 = 0.f, a2 = 0.f, a3 = 0.f;
                #pragma unroll
                for (int k = 0; k < 8; ++k) {
                    a0 = fmaf(wc[k],      hv[k],      a0);
                    a1 = fmaf(wc[k + 8],  hv[k + 8],  a1);
                    a2 = fmaf(wc[k + 16], hv[k + 16], a2);
                    a3 = fmaf(wc[k + 24], hv[k + 24], a3);
                }
                ob[gg * CHUNK + lane] = (((a0 + a1) + (a2 + a3)) + bo);
            }
            __syncthreads();
        }

    } else {
        // ---- Warp B1: layer-1 recurrence (lags A by 2 chunks) ----
        unsigned long long w2[16];
        load_w2(W_hh1, lane, w2);
        float h = h_state[Bb * Hh + b * Hh + lane];
        unsigned int hx1a = (unsigned int)__cvta_generic_to_shared(hx1);
        for (int g = 0; g < NCHUNK + 3; ++g) {
            if (g >= 2 && g <= NCHUNK + 1) {
                int c = g - 2;
                int buf = c & 1;                        // su buffer for chunk c
                float (*dst)[Hh + 1] = sh1[c & 1];
                const float* sv = su[buf][0];           // seeds: plain loads, hoistable
                #pragma unroll 16
                for (int s = 0; s < CHUNK; ++s) {
                    float uv = sv[s * Hh + lane];       // off-chain, non-volatile -> batched
                    STSF(hx1a + lane * 4, h);
                    LOADPN(hx1a, U);
                    float z; DOT16N(w2, uv, z, U);
                    h = htanh(z);
                    dst[s][lane] = h;
                }
            }
            __syncthreads();
        }
        out[(size_t)Bb * Tt + Bb * Hh + b * Hh + lane] = h;          // h_final L1
    }
}

extern "C" void kernel_launch(void* const* d_in, const int* in_sizes, int n_in,
                              void* d_out, int out_size) {
    (void)in_sizes; (void)n_in; (void)out_size;
    rnn_pipe_kernel<<<Bb, 96>>>(
        (const float*)d_in[0],  (const float*)d_in[1],  (const float*)d_in[2],
        (const float*)d_in[3],  (const float*)d_in[4],  (const float*)d_in[5],
        (const float*)d_in[6],  (const float*)d_in[7],  (const float*)d_in[8],
        (const float*)d_in[9],  (const float*)d_in[10], (const float*)d_in[11],
        (float*)d_out);
}

// round 14
// speedup vs baseline: 1.2039x; 1.2039x over previous
#include <cuda_runtime.h>

#define Hh 32
#define Bb 64
#define Tt 16384
#define CHUNK 32
#define NCHUNK (Tt / CHUNK)

__device__ __forceinline__ unsigned long long pk2(float lo, float hi) {
    unsigned long long d; asm("mov.b64 %0,{%1,%2};" : "=l"(d) : "f"(lo), "f"(hi)); return d;
}
__device__ __forceinline__ void upk2(unsigned long long v, float& lo, float& hi) {
    asm("mov.b64 {%0,%1},%2;" : "=f"(lo), "=f"(hi) : "l"(v));
}
__device__ __forceinline__ unsigned long long ffma2(unsigned long long a, unsigned long long b, unsigned long long c) {
    unsigned long long d; asm("fma.rn.f32x2 %0,%1,%2,%3;" : "=l"(d) : "l"(a), "l"(b), "l"(c)); return d;
}
__device__ __forceinline__ unsigned long long fadd2(unsigned long long a, unsigned long long b) {
    unsigned long long d; asm("add.rn.f32x2 %0,%1,%2;" : "=l"(d) : "l"(a), "l"(b)); return d;
}

// hardware tanh (MUFU.TANH, lat ~16)
__device__ __forceinline__ float htanh(float z) {
    float t; asm("tanh.approx.f32 %0,%1;" : "=f"(t) : "f"(z));
    return t;
}

#define LOADPN(sa_, P) \
    unsigned long long P##0,P##1,P##2,P##3,P##4,P##5,P##6,P##7,P##8,P##9,P##a,P##b,P##c,P##d,P##e,P##f; \
    asm volatile("ld.shared.v2.u64 {%0,%1},[%2];"    : "=l"(P##0), "=l"(P##1) : "r"(sa_)); \
    asm volatile("ld.shared.v2.u64 {%0,%1},[%2+16];" : "=l"(P##2), "=l"(P##3) : "r"(sa_)); \
    asm volatile("ld.shared.v2.u64 {%0,%1},[%2+32];" : "=l"(P##4), "=l"(P##5) : "r"(sa_)); \
    asm volatile("ld.shared.v2.u64 {%0,%1},[%2+48];" : "=l"(P##6), "=l"(P##7) : "r"(sa_)); \
    asm volatile("ld.shared.v2.u64 {%0,%1},[%2+64];" : "=l"(P##8), "=l"(P##9) : "r"(sa_)); \
    asm volatile("ld.shared.v2.u64 {%0,%1},[%2+80];" : "=l"(P##a), "=l"(P##b) : "r"(sa_)); \
    asm volatile("ld.shared.v2.u64 {%0,%1},[%2+96];" : "=l"(P##c), "=l"(P##d) : "r"(sa_)); \
    asm volatile("ld.shared.v2.u64 {%0,%1},[%2+112];": "=l"(P##e), "=l"(P##f) : "r"(sa_));

// 2-accumulator dot: issue span (16 x rt3 ~ 48) still hides depth-8 chains,
// and the tail shrinks to fadd2 + unpack + add.
#define DOT16N(w2, seed, res, P) { \
    unsigned long long a0 = pk2(seed, 0.f), a1 = 0ull; \
    a0 = ffma2(w2[0],  P##0, a0); a1 = ffma2(w2[1],  P##1, a1); \
    a0 = ffma2(w2[2],  P##2, a0); a1 = ffma2(w2[3],  P##3, a1); \
    a0 = ffma2(w2[4],  P##4, a0); a1 = ffma2(w2[5],  P##5, a1); \
    a0 = ffma2(w2[6],  P##6, a0); a1 = ffma2(w2[7],  P##7, a1); \
    a0 = ffma2(w2[8],  P##8, a0); a1 = ffma2(w2[9],  P##9, a1); \
    a0 = ffma2(w2[10], P##a, a0); a1 = ffma2(w2[11], P##b, a1); \
    a0 = ffma2(w2[12], P##c, a0); a1 = ffma2(w2[13], P##d, a1); \
    a0 = ffma2(w2[14], P##e, a0); a1 = ffma2(w2[15], P##f, a1); \
    unsigned long long s_ = fadd2(a0, a1); \
    float lo_, hi_; upk2(s_, lo_, hi_); \
    res = lo_ + hi_; }

#define STSF(addr, val) asm volatile("st.shared.f32 [%0], %1;" :: "r"(addr), "f"(val))

// load packed weight rows (plain, unscaled)
__device__ __forceinline__ void load_w2(const float* __restrict__ W, int lane,
                                        unsigned long long* w2) {
    #pragma unroll
    for (int k = 0; k < 16; ++k)
        w2[k] = pk2(W[lane * Hh + 2 * k], W[lane * Hh + 2 * k + 1]);
}

__global__ __launch_bounds__(96, 1) void rnn_pipe_kernel(
    const float* __restrict__ x,        const float* __restrict__ h_state,
    const float* __restrict__ W_ih0,    const float* __restrict__ W_hh0,
    const float* __restrict__ b_ih0,    const float* __restrict__ b_hh0,
    const float* __restrict__ W_ih1,    const float* __restrict__ W_hh1,
    const float* __restrict__ b_ih1,    const float* __restrict__ b_hh1,
    const float* __restrict__ W_out,    const float* __restrict__ b_out,
    float* __restrict__ out)
{
    __shared__ __align__(16) float sh0[2][CHUNK][Hh];   // A -> B2 ring; ALSO A's step exchange
    __shared__ __align__(16) float su [2][CHUNK][Hh];   // B2 -> B1 (bias1 pre-folded)
    __shared__ float sh1[2][CHUNK][Hh + 1];             // B1 -> out stage (padded)
    __shared__ __align__(16) float hx1[Hh];             // warp B1 step exchange

    const int b    = blockIdx.x;
    const int lane = threadIdx.x & 31;
    const int wid  = threadIdx.x >> 5;
    const unsigned FULL = 0xffffffffu;

    if (wid == 0) {
        // ---- Warp A: layer-0 recurrence; exchange through the ring rows ----
        unsigned long long w2[16];
        load_w2(W_hh0, lane, w2);
        const float wi    = W_ih0[lane];
        const float bias0 = b_ih0[lane] + b_hh0[lane];
        float h = h_state[b * Hh + lane];
        unsigned int s0a = (unsigned int)__cvta_generic_to_shared(sh0);

        // Seed the exchange: pretend step -1 wrote buf1 row31 (overwritten in chunk 1
        // before B2 ever consumes chunk-1 data).
        unsigned int rd = s0a + (CHUNK * Hh * 4) + 31 * (Hh * 4);
        STSF(rd + lane * 4, h);

        const float* xb = x + (size_t)b * Tt;
        float xc = xb[lane];
        for (int g = 0; g < NCHUNK + 3; ++g) {
            if (g < NCHUNK) {
                float xn = (g + 1 < NCHUNK) ? xb[(g + 1) * CHUNK + lane] : 0.f;
                unsigned int wr = s0a + (g & 1) * (CHUNK * Hh * 4);
                #pragma unroll 16
                for (int s = 0; s < CHUNK; ++s) {
                    float xterm = fmaf(__shfl_sync(FULL, xc, s), wi, bias0); // off-chain
                    LOADPN(rd, U);                     // row written at step s-1
                    float z; DOT16N(w2, xterm, z, U);
                    h = htanh(z);
                    STSF(wr + lane * 4, h);            // chain STS doubles as ring write
                    rd = wr;
                    wr += Hh * 4;
                }
                xc = xn;
            }
            __syncthreads();
        }
        out[(size_t)Bb * Tt + b * Hh + lane] = h;                    // h_final L0

    } else if (wid == 1) {
        // ---- Warp B2: u-projection (bias1 folded) from h0 ring + output stage ----
        unsigned long long wu[16];
        load_w2(W_ih1, lane, wu);
        const float bias1 = b_ih1[lane] + b_hh1[lane];
        float wc[Hh];
        const float bo = b_out[0];
        #pragma unroll
        for (int k = 0; k < Hh; ++k) wc[k] = W_out[k];
        unsigned int s0a = (unsigned int)__cvta_generic_to_shared(sh0);
        float* ob = out + (size_t)b * Tt;

        for (int g = 0; g < NCHUNK + 3; ++g) {
            if (g >= 1 && g <= NCHUNK) {
                int buf = (g - 1) & 1;
                unsigned int base = s0a + buf * (CHUNK * Hh * 4);
                #pragma unroll 4
                for (int s = 0; s < CHUNK; ++s) {
                    LOADPN(base + s * (Hh * 4), U);
                    float uu; DOT16N(wu, bias1, uu, U);
                    su[buf][s][lane] = uu;
                }
            }
            if (g >= 3) {                               // output stage
                int gg  = g - 3;
                const float* hv = sh1[gg & 1][lane];    // lane = timestep in chunk
                float a0 = 0.f, a1 = 0.f, a2 = 0.f, a3 = 0.f;
                #pragma unroll
                for (int k = 0; k < 8; ++k) {
                    a0 = fmaf(wc[k],      hv[k],      a0);
                    a1 = fmaf(wc[k + 8],  hv[k + 8],  a1);
                    a2 = fmaf(wc[k + 16], hv[k + 16], a2);
                    a3 = fmaf(wc[k + 24], hv[k + 24], a3);
                }
                ob[gg * CHUNK + lane] = (((a0 + a1) + (a2 + a3)) + bo);
            }
            __syncthreads();
        }

    } else {
        // ---- Warp B1: layer-1 recurrence (lags A by 2 chunks) ----
        unsigned long long w2[16];
        load_w2(W_hh1, lane, w2);
        float h = h_state[Bb * Hh + b * Hh + lane];
        unsigned int hx1a = (unsigned int)__cvta_generic_to_shared(hx1);
        for (int g = 0; g < NCHUNK + 3; ++g) {
            if (g >= 2 && g <= NCHUNK + 1) {
                int c = g - 2;
                int buf = c & 1;                        // su buffer for chunk c
                float (*dst)[Hh + 1] = sh1[c & 1];
                const float* sv = su[buf][0];           // seeds: plain loads, hoistable
                #pragma unroll 16
                for (int s = 0; s < CHUNK; ++s) {
                    float uv = sv[s * Hh + lane];       // off-chain, non-volatile -> batched
                    STSF(hx1a + lane * 4, h);
                    LOADPN(hx1a, U);
                    float z; DOT16N(w2, uv, z, U);
                    h = htanh(z);
                    dst[s][lane] = h;
                }
            }
            __syncthreads();
        }
        out[(size_t)Bb * Tt + Bb * Hh + b * Hh + lane] = h;          // h_final L1
    }
}

extern "C" void kernel_launch(void* const* d_in, const int* in_sizes, int n_in,
                              void* d_out, int out_size) {
    (void)in_sizes; (void)n_in; (void)out_size;
    rnn_pipe_kernel<<<Bb, 96>>>(
        (const float*)d_in[0],  (const float*)d_in[1],  (const float*)d_in[2],
        (const float*)d_in[3],  (const float*)d_in[4],  (const float*)d_in[5],
        (const float*)d_in[6],  (const float*)d_in[7],  (const float*)d_in[8],
        (const float*)d_in[9],  (const float*)d_in[10], (const float*)d_in[11],
        (float*)d_out);
}